// round 2
// baseline (speedup 1.0000x reference)
#include <cuda_runtime.h>
#include <cuda_bf16.h>

// Problem constants (fixed by setup_inputs)
#define BD   4      // batch
#define CH   32     // channels
#define NH   4      // heads
#define HD   8      // head_dim
#define HH   256
#define WW   256
#define KS   5      // kernel size (2*amp+1)
#define AMP  2

// Tiling
#define TILE_Y 16
#define TILE_X 32
#define TXN    8            // threads along x
#define P      4            // pixels per thread along x
#define NTHR   128          // 8 x 16 threads
#define SROWS  (TILE_Y + 2*AMP)   // 20
#define SCOLS  (TILE_X + 2*AMP)   // 36

__global__ __launch_bounds__(NTHR, 4)
void cover_kernel(const float* __restrict__ xq,
                  const float* __restrict__ xk,
                  float* __restrict__ out)
{
    // per-head k tile: 8 channels x 20 rows x 36 cols = 23040 B
    __shared__ float sk[HD][SROWS][SCOLS];

    const int tid = threadIdx.x;
    const int tx  = tid & (TXN - 1);   // 0..7
    const int ty  = tid >> 3;          // 0..15
    const int x0  = blockIdx.x * TILE_X;
    const int y0  = blockIdx.y * TILE_Y;
    const int b   = blockIdx.z;
    const int y   = y0 + ty;
    const int xg  = x0 + tx * P;

    // validity bitmasks (offset index di/dj in 0..4 -> spatial offset di-2 / dj-2)
    unsigned rowbits = 0;
    #pragma unroll
    for (int di = 0; di < KS; ++di) {
        int yy = y + di - AMP;
        if (yy >= 0 && yy < HH) rowbits |= (1u << di);
    }
    unsigned colbits[P];
    #pragma unroll
    for (int p = 0; p < P; ++p) {
        unsigned cb = 0;
        #pragma unroll
        for (int dj = 0; dj < KS; ++dj) {
            int xx = xg + p + dj - AMP;
            if (xx >= 0 && xx < WW) cb |= (1u << dj);
        }
        colbits[p] = cb;
    }

    const float scale = 0.35355339059327373f;  // 8^-0.5
    const long  plane = (long)HH * WW;

    const float* xq_b = xq + (long)b * CH * plane;
    const float* xk_b = xk + (long)b * CH * plane;

    float outy[P] = {0.f, 0.f, 0.f, 0.f};
    float outx[P] = {0.f, 0.f, 0.f, 0.f};

    for (int h = 0; h < NH; ++h) {
        __syncthreads();  // previous head's tile fully consumed

        // stage k tile for this head: channels c = d*NH + h, d in [0,8)
        #pragma unroll 1
        for (int idx = tid; idx < HD * SROWS * SCOLS; idx += NTHR) {
            int c   = idx / (SROWS * SCOLS);
            int rem = idx - c * (SROWS * SCOLS);
            int r   = rem / SCOLS;
            int m   = rem - r * SCOLS;
            int gy  = y0 - AMP + r;
            int gx  = x0 - AMP + m;
            float v = 0.f;
            if (gy >= 0 && gy < HH && gx >= 0 && gx < WW)
                v = xk_b[(long)(c * NH + h) * plane + (long)gy * WW + gx];
            sk[c][r][m] = v;
        }
        __syncthreads();

        // q for this head: 8 channels x 4 pixels (aligned float4)
        float q[HD][P];
        #pragma unroll
        for (int c = 0; c < HD; ++c) {
            float4 qv = *reinterpret_cast<const float4*>(
                xq_b + (long)(c * NH + h) * plane + (long)y * WW + xg);
            q[c][0] = qv.x * scale; q[c][1] = qv.y * scale;
            q[c][2] = qv.z * scale; q[c][3] = qv.w * scale;
        }

        // streaming softmax accumulators (no max pass: |score| <~ 8, exp safe)
        float s[P]  = {0.f, 0.f, 0.f, 0.f};
        float oy[P] = {0.f, 0.f, 0.f, 0.f};
        float ox[P] = {0.f, 0.f, 0.f, 0.f};

        #pragma unroll
        for (int di = 0; di < KS; ++di) {
            // scores for this offset-row: a[dj][p], only 20 live regs
            float a[KS][P];
            #pragma unroll
            for (int dj = 0; dj < KS; ++dj)
                #pragma unroll
                for (int p = 0; p < P; ++p) a[dj][p] = 0.f;

            #pragma unroll
            for (int c = 0; c < HD; ++c) {
                const float* krow = &sk[c][ty + di][tx * P];  // 16B aligned
                float4 k0 = *reinterpret_cast<const float4*>(krow);
                float4 k1 = *reinterpret_cast<const float4*>(krow + 4);
                float kk[8] = {k0.x, k0.y, k0.z, k0.w, k1.x, k1.y, k1.z, k1.w};
                #pragma unroll
                for (int dj = 0; dj < KS; ++dj)
                    #pragma unroll
                    for (int p = 0; p < P; ++p)
                        a[dj][p] = fmaf(q[c][p], kk[p + dj], a[dj][p]);
            }

            const bool rvalid = (rowbits >> di) & 1u;
            const float fdi = (float)(di - AMP);
            #pragma unroll
            for (int p = 0; p < P; ++p) {
                const unsigned cb = colbits[p];
                float rs = 0.f, cs = 0.f;
                #pragma unroll
                for (int dj = 0; dj < KS; ++dj) {
                    bool valid = rvalid && ((cb >> dj) & 1u);
                    float w = valid ? __expf(a[dj][p]) : 0.f;
                    rs += w;
                    cs = fmaf(w, (float)(dj - AMP), cs);
                }
                s[p]  += rs;
                oy[p] = fmaf(rs, fdi, oy[p]);
                ox[p] += cs;
            }
        }

        #pragma unroll
        for (int p = 0; p < P; ++p) {
            float inv = __frcp_rn(s[p]);
            outy[p] = fmaf(oy[p], inv, outy[p]);
            outx[p] = fmaf(ox[p], inv, outx[p]);
        }
    }

    // mean over heads, write (B, 2, H, W): ch0 = row offset, ch1 = col offset
    const float invh = 1.0f / (float)NH;
    float* ob = out + (long)b * 2 * plane;
    float4 o0 = make_float4(outy[0] * invh, outy[1] * invh,
                            outy[2] * invh, outy[3] * invh);
    float4 o1 = make_float4(outx[0] * invh, outx[1] * invh,
                            outx[2] * invh, outx[3] * invh);
    *reinterpret_cast<float4*>(ob + (long)y * WW + xg) = o0;
    *reinterpret_cast<float4*>(ob + plane + (long)y * WW + xg) = o1;
}

extern "C" void kernel_launch(void* const* d_in, const int* in_sizes, int n_in,
                              void* d_out, int out_size)
{
    const float* xq = (const float*)d_in[0];
    const float* xk = (const float*)d_in[1];
    float* out = (float*)d_out;
    (void)in_sizes; (void)n_in; (void)out_size;

    dim3 grid(WW / TILE_X, HH / TILE_Y, BD);  // (8, 16, 4)
    cover_kernel<<<grid, NTHR>>>(xq, xk, out);
}

// round 3
// speedup vs baseline: 1.4081x; 1.4081x over previous
#include <cuda_runtime.h>
#include <cstdint>

// Problem constants (fixed by setup_inputs)
#define BD   4
#define NH   4
#define HD   8
#define HH   256
#define WW   256
#define KS   5
#define AMP  2

// Tiling
#define TILE_Y 16
#define TILE_X 32
#define TXN    8
#define P      4
#define NTHR   128
#define SROWS  (TILE_Y + 2*AMP)   // 20
#define SCOLS  (TILE_X + 2*AMP)   // 36
#define HEAD_ELEMS (HD * SROWS * SCOLS)   // 5760

__device__ __forceinline__ uint32_t smem_u32(const void* p) {
    uint32_t a;
    asm("{ .reg .u64 t; cvta.to.shared.u64 t, %1; cvt.u32.u64 %0, t; }"
        : "=r"(a) : "l"(p));
    return a;
}
__device__ __forceinline__ float ex2f(float x) {
    float r; asm("ex2.approx.f32 %0, %1;" : "=f"(r) : "f"(x)); return r;
}
__device__ __forceinline__ float rcpf(float x) {
    float r; asm("rcp.approx.f32 %0, %1;" : "=f"(r) : "f"(x)); return r;
}
__device__ __forceinline__ void cp4(uint32_t s, const float* g, bool v) {
    int sz = v ? 4 : 0;
    asm volatile("cp.async.ca.shared.global [%0], [%1], 4, %2;"
                 :: "r"(s), "l"(g), "r"(sz));
}

// double-buffered per-head k tile: 2 x 8ch x 20 x 36 floats = 46080 B
__shared__ __align__(16) float sk[2][HD][SROWS][SCOLS];

__device__ __forceinline__ void stage_head(const float* __restrict__ xk_b,
                                           int h, int buf,
                                           int x0, int y0, int tid)
{
    uint32_t sbase = smem_u32(&sk[buf][0][0][0]);
    #pragma unroll
    for (int it = 0; it < HEAD_ELEMS / NTHR; ++it) {   // 45 async copies
        int idx = it * NTHR + tid;
        int c   = idx / (SROWS * SCOLS);
        int rem = idx - c * (SROWS * SCOLS);
        int r   = rem / SCOLS;
        int m   = rem - r * SCOLS;
        int gy  = y0 - AMP + r;
        int gx  = x0 - AMP + m;
        bool v  = (gy >= 0) & (gy < HH) & (gx >= 0) & (gx < WW);
        int gyc = v ? gy : 0;
        int gxc = v ? gx : 0;
        const float* g = xk_b + ((c * NH + h) << 16) + (gyc << 8) + gxc;
        cp4(sbase + (uint32_t)idx * 4u, g, v);
    }
    asm volatile("cp.async.commit_group;" ::: "memory");
}

__global__ __launch_bounds__(NTHR, 4)
void cover_kernel(const float* __restrict__ xq,
                  const float* __restrict__ xk,
                  float* __restrict__ out)
{
    const int tid = threadIdx.x;
    const int tx  = tid & (TXN - 1);   // 0..7
    const int ty  = tid >> 3;          // 0..15
    const int x0  = blockIdx.x * TILE_X;
    const int y0  = blockIdx.y * TILE_Y;
    const int b   = blockIdx.z;
    const int y   = y0 + ty;
    const int xg  = x0 + tx * P;

    // validity bitmasks (di/dj in 0..4 -> spatial offset -2..+2)
    unsigned rowbits = 0;
    #pragma unroll
    for (int di = 0; di < KS; ++di) {
        int yy = y + di - AMP;
        if (yy >= 0 && yy < HH) rowbits |= (1u << di);
    }
    unsigned colbits[P];
    #pragma unroll
    for (int p = 0; p < P; ++p) {
        unsigned cb = 0;
        #pragma unroll
        for (int dj = 0; dj < KS; ++dj) {
            int xx = xg + p + dj - AMP;
            if (xx >= 0 && xx < WW) cb |= (1u << dj);
        }
        colbits[p] = cb;
    }
    const bool allvalid = (rowbits == 0x1Fu) &&
        ((colbits[0] & colbits[1] & colbits[2] & colbits[3]) == 0x1Fu);

    // fold log2(e) into q scale: weight = exp2(score*log2e) = exp(score)
    const float qscale = 0.35355339059327373f * 1.4426950408889634f;
    const long plane = (long)HH * WW;

    const float* xq_b = xq + (long)b * (NH * HD) * plane;
    const float* xk_b = xk + (long)b * (NH * HD) * plane;

    float outy[P] = {0.f, 0.f, 0.f, 0.f};
    float outx[P] = {0.f, 0.f, 0.f, 0.f};

    // prologue: stage heads 0 and 1
    stage_head(xk_b, 0, 0, x0, y0, tid);
    stage_head(xk_b, 1, 1, x0, y0, tid);

    #pragma unroll 1
    for (int h = 0; h < NH; ++h) {
        if (h == NH - 1) asm volatile("cp.async.wait_group 0;" ::: "memory");
        else             asm volatile("cp.async.wait_group 1;" ::: "memory");
        __syncthreads();
        const int buf = h & 1;

        // q for this head: 8 channels x 4 pixels
        float q[HD][P];
        #pragma unroll
        for (int c = 0; c < HD; ++c) {
            float4 qv = *reinterpret_cast<const float4*>(
                xq_b + ((c * NH + h) << 16) + (y << 8) + xg);
            q[c][0] = qv.x * qscale; q[c][1] = qv.y * qscale;
            q[c][2] = qv.z * qscale; q[c][3] = qv.w * qscale;
        }

        float s[P]  = {0.f, 0.f, 0.f, 0.f};
        float oy[P] = {0.f, 0.f, 0.f, 0.f};
        float ox[P] = {0.f, 0.f, 0.f, 0.f};

        #pragma unroll
        for (int di = 0; di < KS; ++di) {
            float a[KS][P];
            #pragma unroll
            for (int dj = 0; dj < KS; ++dj)
                #pragma unroll
                for (int p = 0; p < P; ++p) a[dj][p] = 0.f;

            #pragma unroll
            for (int c = 0; c < HD; ++c) {
                const float* krow = &sk[buf][c][ty + di][tx * P];  // 16B aligned
                float4 k0 = *reinterpret_cast<const float4*>(krow);
                float4 k1 = *reinterpret_cast<const float4*>(krow + 4);
                float kk[8] = {k0.x, k0.y, k0.z, k0.w, k1.x, k1.y, k1.z, k1.w};
                #pragma unroll
                for (int dj = 0; dj < KS; ++dj)
                    #pragma unroll
                    for (int p = 0; p < P; ++p)
                        a[dj][p] = fmaf(q[c][p], kk[p + dj], a[dj][p]);
            }

            const float fdi = (float)(di - AMP);
            if (allvalid) {
                #pragma unroll
                for (int p = 0; p < P; ++p) {
                    float rs = 0.f, cs = 0.f;
                    #pragma unroll
                    for (int dj = 0; dj < KS; ++dj) {
                        float w = ex2f(a[dj][p]);
                        rs += w;
                        cs = fmaf(w, (float)(dj - AMP), cs);
                    }
                    s[p]  += rs;
                    oy[p]  = fmaf(rs, fdi, oy[p]);
                    ox[p] += cs;
                }
            } else {
                const bool rvalid = (rowbits >> di) & 1u;
                #pragma unroll
                for (int p = 0; p < P; ++p) {
                    const unsigned cb = colbits[p];
                    float rs = 0.f, cs = 0.f;
                    #pragma unroll
                    for (int dj = 0; dj < KS; ++dj) {
                        bool valid = rvalid && ((cb >> dj) & 1u);
                        float w = valid ? ex2f(a[dj][p]) : 0.f;
                        rs += w;
                        cs = fmaf(w, (float)(dj - AMP), cs);
                    }
                    s[p]  += rs;
                    oy[p]  = fmaf(rs, fdi, oy[p]);
                    ox[p] += cs;
                }
            }
        }

        #pragma unroll
        for (int p = 0; p < P; ++p) {
            float inv = rcpf(s[p]);
            outy[p] = fmaf(oy[p], inv, outy[p]);
            outx[p] = fmaf(ox[p], inv, outx[p]);
        }

        __syncthreads();  // all readers done with buf before restaging it
        if (h + 2 < NH)
            stage_head(xk_b, h + 2, buf, x0, y0, tid);
    }

    // mean over heads, write (B, 2, H, W): ch0 = row offset, ch1 = col offset
    const float invh = 1.0f / (float)NH;
    float* ob = out + (long)b * 2 * plane;
    float4 o0 = make_float4(outy[0] * invh, outy[1] * invh,
                            outy[2] * invh, outy[3] * invh);
    float4 o1 = make_float4(outx[0] * invh, outx[1] * invh,
                            outx[2] * invh, outx[3] * invh);
    *reinterpret_cast<float4*>(ob + (y << 8) + xg) = o0;
    *reinterpret_cast<float4*>(ob + plane + (y << 8) + xg) = o1;
}

extern "C" void kernel_launch(void* const* d_in, const int* in_sizes, int n_in,
                              void* d_out, int out_size)
{
    const float* xq = (const float*)d_in[0];
    const float* xk = (const float*)d_in[1];
    float* out = (float*)d_out;
    (void)in_sizes; (void)n_in; (void)out_size;

    dim3 grid(WW / TILE_X, HH / TILE_Y, BD);  // (8, 16, 4)
    cover_kernel<<<grid, NTHR>>>(xq, xk, out);
}

// round 4
// speedup vs baseline: 1.6079x; 1.1419x over previous
#include <cuda_runtime.h>
#include <cstdint>

// Problem constants (fixed by setup_inputs)
#define BD   4
#define NH   4
#define HD   8
#define HH   256
#define WW   256
#define KS   5
#define AMP  2

// Tiling: 32x16 tile, 256 threads, 2 pixels per thread along x
#define TILE_Y 16
#define TILE_X 32
#define TXN    16
#define P      2
#define NTHR   256
#define SROWS  (TILE_Y + 2*AMP)   // 20
#define SCOLS  (TILE_X + 2*AMP)   // 36
#define HEAD_ELEMS (HD * SROWS * SCOLS)   // 5760

__device__ __forceinline__ uint32_t smem_u32(const void* p) {
    uint32_t a;
    asm("{ .reg .u64 t; cvta.to.shared.u64 t, %1; cvt.u32.u64 %0, t; }"
        : "=r"(a) : "l"(p));
    return a;
}
__device__ __forceinline__ float ex2f(float x) {
    float r; asm("ex2.approx.f32 %0, %1;" : "=f"(r) : "f"(x)); return r;
}
__device__ __forceinline__ float rcpf(float x) {
    float r; asm("rcp.approx.f32 %0, %1;" : "=f"(r) : "f"(x)); return r;
}
__device__ __forceinline__ void cp4(uint32_t s, const float* g, bool v) {
    int sz = v ? 4 : 0;
    asm volatile("cp.async.ca.shared.global [%0], [%1], 4, %2;"
                 :: "r"(s), "l"(g), "r"(sz));
}

__device__ __forceinline__ void stage_head(uint32_t sbase,
                                           const float* __restrict__ xk_b,
                                           int h, int x0, int y0, int tid)
{
    // 5760 elems / 256 threads = 22.5 -> 23 iterations, last half-guarded
    #pragma unroll
    for (int it = 0; it < 23; ++it) {
        int idx = it * NTHR + tid;
        if (it == 22 && idx >= HEAD_ELEMS) break;
        int c   = idx / (SROWS * SCOLS);
        int rem = idx - c * (SROWS * SCOLS);
        int r   = rem / SCOLS;
        int m   = rem - r * SCOLS;
        int gy  = y0 - AMP + r;
        int gx  = x0 - AMP + m;
        bool v  = (gy >= 0) & (gy < HH) & (gx >= 0) & (gx < WW);
        int gyc = v ? gy : 0;
        int gxc = v ? gx : 0;
        const float* g = xk_b + ((c * NH + h) << 16) + (gyc << 8) + gxc;
        cp4(sbase + (uint32_t)idx * 4u, g, v);
    }
    asm volatile("cp.async.commit_group;" ::: "memory");
}

__global__ __launch_bounds__(NTHR, 4)
void cover_kernel(const float* __restrict__ xq,
                  const float* __restrict__ xk,
                  float* __restrict__ out)
{
    // double-buffered per-head k tile: 2 x 8ch x 20 x 36 floats = 46080 B
    __shared__ __align__(16) float sk[2][HD][SROWS][SCOLS];

    const int tid = threadIdx.x;
    const int tx  = tid & (TXN - 1);   // 0..15
    const int ty  = tid >> 4;          // 0..15
    const int x0  = blockIdx.x * TILE_X;
    const int y0  = blockIdx.y * TILE_Y;
    const int b   = blockIdx.z;
    const int y   = y0 + ty;
    const int xg  = x0 + tx * P;

    const uint32_t sb0 = smem_u32(&sk[0][0][0][0]);
    const uint32_t sb1 = smem_u32(&sk[1][0][0][0]);

    // validity bitmasks (di/dj in 0..4 -> spatial offset -2..+2)
    unsigned rowbits = 0;
    #pragma unroll
    for (int di = 0; di < KS; ++di) {
        int yy = y + di - AMP;
        if (yy >= 0 && yy < HH) rowbits |= (1u << di);
    }
    unsigned colbits[P];
    #pragma unroll
    for (int p = 0; p < P; ++p) {
        unsigned cb = 0;
        #pragma unroll
        for (int dj = 0; dj < KS; ++dj) {
            int xx = xg + p + dj - AMP;
            if (xx >= 0 && xx < WW) cb |= (1u << dj);
        }
        colbits[p] = cb;
    }
    const bool allvalid = (rowbits == 0x1Fu) &&
        ((colbits[0] & colbits[1]) == 0x1Fu);

    // fold log2(e) into q scale: exp(score) = exp2(score*log2e)
    const float qscale = 0.35355339059327373f * 1.4426950408889634f;
    const long plane = (long)HH * WW;

    const float* xq_b = xq + (long)b * (NH * HD) * plane;
    const float* xk_b = xk + (long)b * (NH * HD) * plane;

    float outy[P] = {0.f, 0.f};
    float outx[P] = {0.f, 0.f};

    // prologue: stage heads 0 and 1
    stage_head(sb0, xk_b, 0, x0, y0, tid);
    stage_head(sb1, xk_b, 1, x0, y0, tid);

    #pragma unroll 1
    for (int h = 0; h < NH; ++h) {
        if (h == NH - 1) asm volatile("cp.async.wait_group 0;" ::: "memory");
        else             asm volatile("cp.async.wait_group 1;" ::: "memory");
        __syncthreads();
        const int buf = h & 1;

        // q for this head: 8 channels x 2 pixels (8B-aligned float2)
        float q[HD][P];
        #pragma unroll
        for (int c = 0; c < HD; ++c) {
            float2 qv = *reinterpret_cast<const float2*>(
                xq_b + ((c * NH + h) << 16) + (y << 8) + xg);
            q[c][0] = qv.x * qscale;
            q[c][1] = qv.y * qscale;
        }

        float s[P]  = {0.f, 0.f};
        float oy[P] = {0.f, 0.f};
        float ox[P] = {0.f, 0.f};

        #pragma unroll
        for (int di = 0; di < KS; ++di) {
            float a[KS][P];
            #pragma unroll
            for (int dj = 0; dj < KS; ++dj)
                #pragma unroll
                for (int p = 0; p < P; ++p) a[dj][p] = 0.f;

            #pragma unroll
            for (int c = 0; c < HD; ++c) {
                const float* krow = &sk[buf][c][ty + di][tx * P];  // 8B aligned
                float2 k01 = *reinterpret_cast<const float2*>(krow);
                float2 k23 = *reinterpret_cast<const float2*>(krow + 2);
                float2 k45 = *reinterpret_cast<const float2*>(krow + 4);
                float kk[6] = {k01.x, k01.y, k23.x, k23.y, k45.x, k45.y};
                #pragma unroll
                for (int dj = 0; dj < KS; ++dj)
                    #pragma unroll
                    for (int p = 0; p < P; ++p)
                        a[dj][p] = fmaf(q[c][p], kk[p + dj], a[dj][p]);
            }

            const float fdi = (float)(di - AMP);
            if (allvalid) {
                #pragma unroll
                for (int p = 0; p < P; ++p) {
                    float rs = 0.f, cs = 0.f;
                    #pragma unroll
                    for (int dj = 0; dj < KS; ++dj) {
                        float w = ex2f(a[dj][p]);
                        rs += w;
                        cs = fmaf(w, (float)(dj - AMP), cs);
                    }
                    s[p]  += rs;
                    oy[p]  = fmaf(rs, fdi, oy[p]);
                    ox[p] += cs;
                }
            } else {
                const bool rvalid = (rowbits >> di) & 1u;
                #pragma unroll
                for (int p = 0; p < P; ++p) {
                    const unsigned cb = colbits[p];
                    float rs = 0.f, cs = 0.f;
                    #pragma unroll
                    for (int dj = 0; dj < KS; ++dj) {
                        bool valid = rvalid && ((cb >> dj) & 1u);
                        float w = valid ? ex2f(a[dj][p]) : 0.f;
                        rs += w;
                        cs = fmaf(w, (float)(dj - AMP), cs);
                    }
                    s[p]  += rs;
                    oy[p]  = fmaf(rs, fdi, oy[p]);
                    ox[p] += cs;
                }
            }
        }

        #pragma unroll
        for (int p = 0; p < P; ++p) {
            float inv = rcpf(s[p]);
            outy[p] = fmaf(oy[p], inv, outy[p]);
            outx[p] = fmaf(ox[p], inv, outx[p]);
        }

        __syncthreads();  // all readers done with buf before restaging it
        if (h + 2 < NH)
            stage_head(buf ? sb1 : sb0, xk_b, h + 2, x0, y0, tid);
    }

    // mean over heads, write (B, 2, H, W): ch0 = row offset, ch1 = col offset
    const float invh = 1.0f / (float)NH;
    float* ob = out + (long)b * 2 * plane;
    float2 o0 = make_float2(outy[0] * invh, outy[1] * invh);
    float2 o1 = make_float2(outx[0] * invh, outx[1] * invh);
    *reinterpret_cast<float2*>(ob + (y << 8) + xg) = o0;
    *reinterpret_cast<float2*>(ob + plane + (y << 8) + xg) = o1;
}

extern "C" void kernel_launch(void* const* d_in, const int* in_sizes, int n_in,
                              void* d_out, int out_size)
{
    const float* xq = (const float*)d_in[0];
    const float* xk = (const float*)d_in[1];
    float* out = (float*)d_out;
    (void)in_sizes; (void)n_in; (void)out_size;

    dim3 grid(WW / TILE_X, HH / TILE_Y, BD);  // (8, 16, 4)
    cover_kernel<<<grid, NTHR>>>(xq, xk, out);
}

// round 5
// speedup vs baseline: 1.6210x; 1.0081x over previous
#include <cuda_runtime.h>
#include <cstdint>

// Problem constants (fixed by setup_inputs)
#define BD   4
#define NH   4
#define HD   8
#define HH   256
#define WW   256
#define KS   5
#define AMP  2

// Tiling: 32x16 tile, 256 threads, 2 pixels per thread along x
#define TILE_Y 16
#define TILE_X 32
#define TXN    16
#define P      2
#define NTHR   256
#define SROWS  (TILE_Y + 2*AMP)   // 20
#define SCOLS  (TILE_X + 2*AMP)   // 36
#define HEAD_ELEMS (HD * SROWS * SCOLS)   // 5760

__device__ __forceinline__ uint32_t smem_u32(const void* p) {
    uint32_t a;
    asm("{ .reg .u64 t; cvta.to.shared.u64 t, %1; cvt.u32.u64 %0, t; }"
        : "=r"(a) : "l"(p));
    return a;
}
__device__ __forceinline__ float ex2f(float x) {
    float r; asm("ex2.approx.f32 %0, %1;" : "=f"(r) : "f"(x)); return r;
}
__device__ __forceinline__ float rcpf(float x) {
    float r; asm("rcp.approx.f32 %0, %1;" : "=f"(r) : "f"(x)); return r;
}
__device__ __forceinline__ void cp4(uint32_t s, const float* g, bool v) {
    int sz = v ? 4 : 0;
    asm volatile("cp.async.ca.shared.global [%0], [%1], 4, %2;"
                 :: "r"(s), "l"(g), "r"(sz));
}
// packed d += a * b  (Blackwell FFMA2 — ptxas never auto-fuses this)
__device__ __forceinline__ void ffma2(float2& d, const float2 a, const float2 b) {
    asm("{\n\t"
        ".reg .b64 ra, rb, rd;\n\t"
        "mov.b64 ra, {%2, %3};\n\t"
        "mov.b64 rb, {%4, %5};\n\t"
        "mov.b64 rd, {%0, %1};\n\t"
        "fma.rn.f32x2 rd, ra, rb, rd;\n\t"
        "mov.b64 {%0, %1}, rd;\n\t"
        "}"
        : "+f"(d.x), "+f"(d.y)
        : "f"(a.x), "f"(a.y), "f"(b.x), "f"(b.y));
}
__device__ __forceinline__ float2 fmul2(const float2 a, const float2 b) {
    float2 d;
    asm("{\n\t"
        ".reg .b64 ra, rb, rd;\n\t"
        "mov.b64 ra, {%2, %3};\n\t"
        "mov.b64 rb, {%4, %5};\n\t"
        "mul.rn.f32x2 rd, ra, rb;\n\t"
        "mov.b64 {%0, %1}, rd;\n\t"
        "}"
        : "=f"(d.x), "=f"(d.y)
        : "f"(a.x), "f"(a.y), "f"(b.x), "f"(b.y));
    return d;
}

__device__ __forceinline__ void stage_head(uint32_t sbase,
                                           const float* __restrict__ xk_b,
                                           int h, int x0, int y0, int tid)
{
    // 5760 elems / 256 threads = 22.5 -> 23 iterations, last half-guarded
    #pragma unroll
    for (int it = 0; it < 23; ++it) {
        int idx = it * NTHR + tid;
        if (it == 22 && idx >= HEAD_ELEMS) break;
        int c   = idx / (SROWS * SCOLS);
        int rem = idx - c * (SROWS * SCOLS);
        int r   = rem / SCOLS;
        int m   = rem - r * SCOLS;
        int gy  = y0 - AMP + r;
        int gx  = x0 - AMP + m;
        bool v  = (gy >= 0) & (gy < HH) & (gx >= 0) & (gx < WW);
        int gyc = v ? gy : 0;
        int gxc = v ? gx : 0;
        const float* g = xk_b + ((c * NH + h) << 16) + (gyc << 8) + gxc;
        cp4(sbase + (uint32_t)idx * 4u, g, v);
    }
    asm volatile("cp.async.commit_group;" ::: "memory");
}

__global__ __launch_bounds__(NTHR, 4)
void cover_kernel(const float* __restrict__ xq,
                  const float* __restrict__ xk,
                  float* __restrict__ out)
{
    // double-buffered per-head k tile: 2 x 8ch x 20 x 36 floats = 46080 B
    __shared__ __align__(16) float sk[2][HD][SROWS][SCOLS];

    const int tid = threadIdx.x;
    const int tx  = tid & (TXN - 1);   // 0..15
    const int ty  = tid >> 4;          // 0..15
    const int x0  = blockIdx.x * TILE_X;
    const int y0  = blockIdx.y * TILE_Y;
    const int b   = blockIdx.z;
    const int y   = y0 + ty;
    const int xg  = x0 + tx * P;

    const uint32_t sb0 = smem_u32(&sk[0][0][0][0]);
    const uint32_t sb1 = smem_u32(&sk[1][0][0][0]);

    // validity bitmasks (di/dj in 0..4 -> spatial offset -2..+2)
    unsigned rowbits = 0;
    #pragma unroll
    for (int di = 0; di < KS; ++di) {
        int yy = y + di - AMP;
        if (yy >= 0 && yy < HH) rowbits |= (1u << di);
    }
    unsigned colbits[P];
    #pragma unroll
    for (int p = 0; p < P; ++p) {
        unsigned cb = 0;
        #pragma unroll
        for (int dj = 0; dj < KS; ++dj) {
            int xx = xg + p + dj - AMP;
            if (xx >= 0 && xx < WW) cb |= (1u << dj);
        }
        colbits[p] = cb;
    }
    const bool allvalid = (rowbits == 0x1Fu) &&
        ((colbits[0] & colbits[1]) == 0x1Fu);

    // fold log2(e) into q scale: exp(score) = exp2(score*log2e)
    const float qscale = 0.35355339059327373f * 1.4426950408889634f;
    const float2 qs2 = make_float2(qscale, qscale);
    const long plane = (long)HH * WW;

    const float* xq_b = xq + (long)b * (NH * HD) * plane;
    const float* xk_b = xk + (long)b * (NH * HD) * plane;

    float outy[P] = {0.f, 0.f};
    float outx[P] = {0.f, 0.f};

    // prologue: stage heads 0 and 1
    stage_head(sb0, xk_b, 0, x0, y0, tid);
    stage_head(sb1, xk_b, 1, x0, y0, tid);

    #pragma unroll 1
    for (int h = 0; h < NH; ++h) {
        if (h == NH - 1) asm volatile("cp.async.wait_group 0;" ::: "memory");
        else             asm volatile("cp.async.wait_group 1;" ::: "memory");
        __syncthreads();
        const int buf = h & 1;

        // q for this head: 8 channels x 2 pixels, packed f32x2 scale
        float2 q2[HD];
        #pragma unroll
        for (int c = 0; c < HD; ++c) {
            float2 qv = *reinterpret_cast<const float2*>(
                xq_b + ((c * NH + h) << 16) + (y << 8) + xg);
            q2[c] = fmul2(qv, qs2);
        }

        float s[P]  = {0.f, 0.f};
        float oy[P] = {0.f, 0.f};
        float ox[P] = {0.f, 0.f};

        #pragma unroll
        for (int di = 0; di < KS; ++di) {
            // a2[dj] = packed scores for pixels (p0, p1)
            float2 a2[KS];
            #pragma unroll
            for (int dj = 0; dj < KS; ++dj) a2[dj] = make_float2(0.f, 0.f);

            #pragma unroll
            for (int c = 0; c < HD; ++c) {
                const float* krow = &sk[buf][c][ty + di][tx * P];  // 8B aligned
                float2 k01 = *reinterpret_cast<const float2*>(krow);
                float2 k23 = *reinterpret_cast<const float2*>(krow + 2);
                float2 k45 = *reinterpret_cast<const float2*>(krow + 4);
                // even dj: operand pair == an LDS.64 register pair (free)
                ffma2(a2[0], q2[c], k01);
                ffma2(a2[2], q2[c], k23);
                ffma2(a2[4], q2[c], k45);
                // odd dj: scalar FFMA on the pair halves (aliased, free)
                a2[1].x = fmaf(q2[c].x, k01.y, a2[1].x);
                a2[1].y = fmaf(q2[c].y, k23.x, a2[1].y);
                a2[3].x = fmaf(q2[c].x, k23.y, a2[3].x);
                a2[3].y = fmaf(q2[c].y, k45.x, a2[3].y);
            }

            const float fdi = (float)(di - AMP);
            if (allvalid) {
                #pragma unroll
                for (int p = 0; p < P; ++p) {
                    float w0 = ex2f(p ? a2[0].y : a2[0].x);
                    float w1 = ex2f(p ? a2[1].y : a2[1].x);
                    float w2 = ex2f(p ? a2[2].y : a2[2].x);
                    float w3 = ex2f(p ? a2[3].y : a2[3].x);
                    float w4 = ex2f(p ? a2[4].y : a2[4].x);
                    float rs = ((w0 + w1) + (w2 + w3)) + w4;
                    float cs = fmaf(2.f, w4 - w0, w3 - w1);
                    s[p]  += rs;
                    oy[p]  = fmaf(rs, fdi, oy[p]);
                    ox[p] += cs;
                }
            } else {
                const bool rvalid = (rowbits >> di) & 1u;
                #pragma unroll
                for (int p = 0; p < P; ++p) {
                    const unsigned cb = colbits[p];
                    float a[KS] = {p ? a2[0].y : a2[0].x, p ? a2[1].y : a2[1].x,
                                   p ? a2[2].y : a2[2].x, p ? a2[3].y : a2[3].x,
                                   p ? a2[4].y : a2[4].x};
                    float w[KS];
                    #pragma unroll
                    for (int dj = 0; dj < KS; ++dj) {
                        bool valid = rvalid && ((cb >> dj) & 1u);
                        w[dj] = valid ? ex2f(a[dj]) : 0.f;
                    }
                    float rs = ((w[0] + w[1]) + (w[2] + w[3])) + w[4];
                    float cs = fmaf(2.f, w[4] - w[0], w[3] - w[1]);
                    s[p]  += rs;
                    oy[p]  = fmaf(rs, fdi, oy[p]);
                    ox[p] += cs;
                }
            }
        }

        #pragma unroll
        for (int p = 0; p < P; ++p) {
            float inv = rcpf(s[p]);
            outy[p] = fmaf(oy[p], inv, outy[p]);
            outx[p] = fmaf(ox[p], inv, outx[p]);
        }

        __syncthreads();  // all readers done with buf before restaging it
        if (h + 2 < NH)
            stage_head(buf ? sb1 : sb0, xk_b, h + 2, x0, y0, tid);
    }

    // mean over heads, write (B, 2, H, W): ch0 = row offset, ch1 = col offset
    const float invh = 1.0f / (float)NH;
    float* ob = out + (long)b * 2 * plane;
    float2 o0 = make_float2(outy[0] * invh, outy[1] * invh);
    float2 o1 = make_float2(outx[0] * invh, outx[1] * invh);
    *reinterpret_cast<float2*>(ob + (y << 8) + xg) = o0;
    *reinterpret_cast<float2*>(ob + plane + (y << 8) + xg) = o1;
}

extern "C" void kernel_launch(void* const* d_in, const int* in_sizes, int n_in,
                              void* d_out, int out_size)
{
    const float* xq = (const float*)d_in[0];
    const float* xk = (const float*)d_in[1];
    float* out = (float*)d_out;
    (void)in_sizes; (void)n_in; (void)out_size;

    dim3 grid(WW / TILE_X, HH / TILE_Y, BD);  // (8, 16, 4)
    cover_kernel<<<grid, NTHR>>>(xq, xk, out);
}